// round 1
// baseline (speedup 1.0000x reference)
#include <cuda_runtime.h>
#include <math.h>

// Problem constants
#define DIMC   64
#define KBANK  4
#define BATCH  16
#define HIN    256
#define WIN    256
#define KSZ    5
#define HO     127
#define WO     127
#define OUT_SPATIAL (HO*WO)                       // 16129
#define OUT_OFFSET  (BATCH*DIMC*OUT_SPATIAL)      // 16516096 : start of w_ret in d_out

// Conv tiling
#define TY 32
#define TX 32
#define CTILE 16      // couts per block
#define CCHUNK 2      // cins per smem stage
#define PATCH 67      // (32-1)*2 + 5
#define PATCH_W 68

// Scratch (no allocations allowed)
__device__ float g_pooled[BATCH*DIMC];
__device__ float g_att[BATCH*KBANK];
__device__ float g_aggb[BATCH*DIMC];
__device__ float g_aggw[BATCH*DIMC*DIMC*KSZ*KSZ];   // 6.55 MB

// ---------------------------------------------------------------------------
// 1) Global average pool: one block per (b,c) plane of 256x256
// ---------------------------------------------------------------------------
__global__ void pool_kernel(const float* __restrict__ x) {
    int plane = blockIdx.x;  // b*64 + c
    const float4* p = (const float4*)(x + (size_t)plane * (HIN*WIN));
    float s = 0.f;
    for (int i = threadIdx.x; i < (HIN*WIN)/4; i += 256) {
        float4 v = p[i];
        s += (v.x + v.y) + (v.z + v.w);
    }
    #pragma unroll
    for (int o = 16; o > 0; o >>= 1) s += __shfl_xor_sync(0xffffffffu, s, o);
    __shared__ float ws[8];
    if ((threadIdx.x & 31) == 0) ws[threadIdx.x >> 5] = s;
    __syncthreads();
    if (threadIdx.x == 0) {
        float t = 0.f;
        #pragma unroll
        for (int i = 0; i < 8; i++) t += ws[i];
        g_pooled[plane] = t * (1.0f / (float)(HIN*WIN));
    }
}

// ---------------------------------------------------------------------------
// 2) Attention MLP + softmax + aggregated bias. One thread per batch sample.
// ---------------------------------------------------------------------------
__global__ void att_kernel(const float* __restrict__ fc1_w, const float* __restrict__ fc1_b,
                           const float* __restrict__ fc2_w, const float* __restrict__ fc2_b,
                           const float* __restrict__ bias) {
    int b = threadIdx.x;
    if (b >= BATCH) return;
    float a[KBANK];
    #pragma unroll
    for (int k = 0; k < KBANK; k++) {
        float s = fc1_b[k];
        for (int c = 0; c < DIMC; c++) s += fc1_w[k*DIMC + c] * g_pooled[b*DIMC + c];
        a[k] = fmaxf(s, 0.f);
    }
    float l[KBANK]; float mx = -1e30f;
    #pragma unroll
    for (int k = 0; k < KBANK; k++) {
        float s = fc2_b[k];
        #pragma unroll
        for (int j = 0; j < KBANK; j++) s += fc2_w[k*KBANK + j] * a[j];
        l[k] = s; mx = fmaxf(mx, s);
    }
    float den = 0.f;
    #pragma unroll
    for (int k = 0; k < KBANK; k++) { l[k] = expf(l[k] - mx); den += l[k]; }
    float inv = 1.0f / den;
    #pragma unroll
    for (int k = 0; k < KBANK; k++) { l[k] *= inv; g_att[b*KBANK + k] = l[k]; }
    for (int o = 0; o < DIMC; o++) {
        float s = 0.f;
        #pragma unroll
        for (int k = 0; k < KBANK; k++) s += l[k] * bias[k*DIMC + o];
        g_aggb[b*DIMC + o] = s;
    }
}

// ---------------------------------------------------------------------------
// 3) Mix the K kernel banks per sample; also writes w_ret part of output.
//    agg_w[b,o,i,s] = sum_k att[b,k] * weight[k,o,i,s]
//    w_ret[(b*64+o), s, i] = agg_w[b,o,i,s]
// ---------------------------------------------------------------------------
__global__ void aggw_kernel(const float* __restrict__ weight, float* __restrict__ out) {
    const int PER_B = DIMC*DIMC*KSZ*KSZ;   // 102400
    int idx = blockIdx.x * 256 + threadIdx.x;
    if (idx >= BATCH*PER_B) return;
    int b = idx / PER_B;
    int r = idx - b*PER_B;                 // encodes (o,i,s)
    int o  = r / (DIMC*KSZ*KSZ);
    int r2 = r - o*(DIMC*KSZ*KSZ);
    int i  = r2 / (KSZ*KSZ);
    int s  = r2 - i*(KSZ*KSZ);
    float v = 0.f;
    #pragma unroll
    for (int k = 0; k < KBANK; k++)
        v += g_att[b*KBANK + k] * weight[(size_t)k*PER_B + r];
    g_aggw[idx] = v;
    out[(size_t)OUT_OFFSET + ((size_t)(b*DIMC + o)*(KSZ*KSZ) + s)*DIMC + i] = v;
}

// ---------------------------------------------------------------------------
// 4) Per-sample conv, stride 2 pad 1. Block = (b, 16-cout group, 32x32 tile).
//    Thread: 32 lanes across x, 8 rows of 4 outputs in y; 16 couts -> 64 acc.
// ---------------------------------------------------------------------------
__global__ __launch_bounds__(256) void conv_kernel(const float* __restrict__ x,
                                                   float* __restrict__ out) {
    __shared__ float s_in[CCHUNK][PATCH*PATCH_W];
    __shared__ float s_w[CCHUNK][CTILE][KSZ*KSZ];
    __shared__ float s_b[CTILE];

    const int b     = blockIdx.z;
    const int cg    = blockIdx.y;
    const int tileX = blockIdx.x & 3;
    const int tileY = blockIdx.x >> 2;
    const int coutBase = cg * CTILE;

    const int tid = threadIdx.x;
    const int ltx = tid & 31;
    const int lty = tid >> 5;   // 0..7

    if (tid < CTILE) s_b[tid] = g_aggb[b*DIMC + coutBase + tid];

    float acc[CTILE][4];
    #pragma unroll
    for (int co = 0; co < CTILE; co++)
        #pragma unroll
        for (int dy = 0; dy < 4; dy++) acc[co][dy] = 0.f;

    const int iy0 = tileY*TY*2 - 1;
    const int ix0 = tileX*TX*2 - 1;
    const float* xb = x + (size_t)b * DIMC * HIN * WIN;

    for (int cb = 0; cb < DIMC; cb += CCHUNK) {
        __syncthreads();
        // stage input patch (CCHUNK cins, 67x67 with zero pad at borders)
        for (int p = tid; p < CCHUNK*PATCH*PATCH; p += 256) {
            int ci = p / (PATCH*PATCH);
            int q  = p - ci*(PATCH*PATCH);
            int r  = q / PATCH;
            int c  = q - r*PATCH;
            int iy = iy0 + r, ix = ix0 + c;
            float v = 0.f;
            if ((unsigned)iy < HIN && (unsigned)ix < WIN)
                v = xb[((size_t)(cb + ci)*HIN + iy)*WIN + ix];
            s_in[ci][r*PATCH_W + c] = v;
        }
        // stage weights for this (cout group, cin chunk)
        for (int p = tid; p < CCHUNK*CTILE*KSZ*KSZ; p += 256) {
            int ci = p / (CTILE*KSZ*KSZ);
            int q  = p - ci*(CTILE*KSZ*KSZ);
            int co = q / (KSZ*KSZ);
            int s  = q - co*(KSZ*KSZ);
            s_w[ci][co][s] =
                g_aggw[(((size_t)b*DIMC + coutBase + co)*DIMC + (cb + ci))*(KSZ*KSZ) + s];
        }
        __syncthreads();

        #pragma unroll
        for (int ci = 0; ci < CCHUNK; ci++) {
            #pragma unroll
            for (int ky = 0; ky < KSZ; ky++) {
                #pragma unroll
                for (int kx = 0; kx < KSZ; kx++) {
                    float v[4];
                    #pragma unroll
                    for (int dy = 0; dy < 4; dy++)
                        v[dy] = s_in[ci][((lty*4 + dy)*2 + ky)*PATCH_W + (ltx*2 + kx)];
                    #pragma unroll
                    for (int co = 0; co < CTILE; co++) {
                        float w = s_w[ci][co][ky*KSZ + kx];
                        #pragma unroll
                        for (int dy = 0; dy < 4; dy++)
                            acc[co][dy] = fmaf(w, v[dy], acc[co][dy]);
                    }
                }
            }
        }
    }

    const int ox = tileX*TX + ltx;
    if (ox < WO) {
        #pragma unroll
        for (int co = 0; co < CTILE; co++) {
            float bb = s_b[co];
            size_t base = ((size_t)(b*DIMC + coutBase + co))*OUT_SPATIAL;
            #pragma unroll
            for (int dy = 0; dy < 4; dy++) {
                int oy = tileY*TY + lty*4 + dy;
                if (oy < HO)
                    out[base + (size_t)oy*WO + ox] = acc[co][dy] + bb;
            }
        }
    }
}

// ---------------------------------------------------------------------------
extern "C" void kernel_launch(void* const* d_in, const int* in_sizes, int n_in,
                              void* d_out, int out_size) {
    const float* x     = (const float*)d_in[0];
    const float* fc1_w = (const float*)d_in[1];
    const float* fc1_b = (const float*)d_in[2];
    const float* fc2_w = (const float*)d_in[3];
    const float* fc2_b = (const float*)d_in[4];
    const float* weight= (const float*)d_in[5];
    const float* bias  = (const float*)d_in[6];
    float* out = (float*)d_out;

    pool_kernel<<<BATCH*DIMC, 256>>>(x);
    att_kernel<<<1, 32>>>(fc1_w, fc1_b, fc2_w, fc2_b, bias);
    {
        int n = BATCH*DIMC*DIMC*KSZ*KSZ;
        aggw_kernel<<<(n + 255)/256, 256>>>(weight, out);
    }
    {
        dim3 grid(16, DIMC/CTILE, BATCH);   // 16 spatial tiles x 4 cout groups x 16 batch
        conv_kernel<<<grid, 256>>>(x, out);
    }
    (void)in_sizes; (void)n_in; (void)out_size;
}

// round 2
// speedup vs baseline: 2.2292x; 2.2292x over previous
#include <cuda_runtime.h>
#include <mma.h>
#include <math.h>

using namespace nvcuda;

// Problem constants
#define DIMC   64
#define KBANK  4
#define BATCH  16
#define HIN    256
#define WIN    256
#define KSZ    5
#define HO     127
#define WO     127
#define OUT_SPATIAL (HO*WO)                       // 16129
#define OUT_OFFSET  (BATCH*DIMC*OUT_SPATIAL)      // start of w_ret in d_out

// Conv (implicit GEMM) tiling
#define BM 128          // spatial positions per block (8 oy x 16 ox)
#define BN 64           // couts per block
#define BKC 32          // cin chunk per stage
#define LDA 40          // sA leading dim (floats)
#define LDB 72          // sB leading dim (floats)
#define LDE 68          // epilogue leading dim (floats)

// Scratch (static device arrays — no allocations allowed)
__device__ float g_pooled[BATCH*DIMC];
__device__ float g_aggb[BATCH*DIMC];
__device__ float g_wmat[BATCH*KSZ*KSZ*DIMC*DIMC];         // [b][s][ci][co], tf32-rounded
__device__ float g_xt[(size_t)BATCH*HIN*WIN*DIMC];        // NHWC, tf32-rounded (256 MB)

// ---------------------------------------------------------------------------
// 0) Transpose NCHW -> NHWC with tf32 rounding
// ---------------------------------------------------------------------------
__global__ __launch_bounds__(256) void transpose_kernel(const float* __restrict__ x) {
    __shared__ float s[64][65];
    const int b = blockIdx.z, h = blockIdx.y, w0 = blockIdx.x * 64;
    const int tid = threadIdx.x;
    #pragma unroll
    for (int it = 0; it < 16; it++) {
        int f = it*256 + tid;
        int c = f >> 6, wl = f & 63;
        s[c][wl] = x[(((size_t)(b*DIMC + c))*HIN + h)*WIN + w0 + wl];
    }
    __syncthreads();
    #pragma unroll
    for (int it = 0; it < 16; it++) {
        int f = it*256 + tid;
        int wl = f >> 6, c = f & 63;
        g_xt[(((size_t)b*HIN + h)*WIN + (w0 + wl))*DIMC + c] =
            wmma::__float_to_tf32(s[c][wl]);
    }
}

// ---------------------------------------------------------------------------
// 1) Global average pool: one block per (b,c) plane
// ---------------------------------------------------------------------------
__global__ void pool_kernel(const float* __restrict__ x) {
    int plane = blockIdx.x;
    const float4* p = (const float4*)(x + (size_t)plane * (HIN*WIN));
    float s = 0.f;
    for (int i = threadIdx.x; i < (HIN*WIN)/4; i += 256) {
        float4 v = p[i];
        s += (v.x + v.y) + (v.z + v.w);
    }
    #pragma unroll
    for (int o = 16; o > 0; o >>= 1) s += __shfl_xor_sync(0xffffffffu, s, o);
    __shared__ float ws[8];
    if ((threadIdx.x & 31) == 0) ws[threadIdx.x >> 5] = s;
    __syncthreads();
    if (threadIdx.x == 0) {
        float t = 0.f;
        #pragma unroll
        for (int i = 0; i < 8; i++) t += ws[i];
        g_pooled[plane] = t * (1.0f / (float)(HIN*WIN));
    }
}

// ---------------------------------------------------------------------------
// 2) Attention MLP + softmax + aggregated bias
// ---------------------------------------------------------------------------
__device__ float g_att[BATCH*KBANK];

__global__ void att_kernel(const float* __restrict__ fc1_w, const float* __restrict__ fc1_b,
                           const float* __restrict__ fc2_w, const float* __restrict__ fc2_b,
                           const float* __restrict__ bias) {
    int b = threadIdx.x;
    if (b >= BATCH) return;
    float a[KBANK];
    #pragma unroll
    for (int k = 0; k < KBANK; k++) {
        float s = fc1_b[k];
        for (int c = 0; c < DIMC; c++) s += fc1_w[k*DIMC + c] * g_pooled[b*DIMC + c];
        a[k] = fmaxf(s, 0.f);
    }
    float l[KBANK]; float mx = -1e30f;
    #pragma unroll
    for (int k = 0; k < KBANK; k++) {
        float s = fc2_b[k];
        #pragma unroll
        for (int j = 0; j < KBANK; j++) s += fc2_w[k*KBANK + j] * a[j];
        l[k] = s; mx = fmaxf(mx, s);
    }
    float den = 0.f;
    #pragma unroll
    for (int k = 0; k < KBANK; k++) { l[k] = expf(l[k] - mx); den += l[k]; }
    float inv = 1.0f / den;
    #pragma unroll
    for (int k = 0; k < KBANK; k++) { l[k] *= inv; g_att[b*KBANK + k] = l[k]; }
    for (int o = 0; o < DIMC; o++) {
        float s = 0.f;
        #pragma unroll
        for (int k = 0; k < KBANK; k++) s += l[k] * bias[k*DIMC + o];
        g_aggb[b*DIMC + o] = s;
    }
}

// ---------------------------------------------------------------------------
// 3) Mix kernel banks; write exact w_ret to out, tf32 wmat for conv
// ---------------------------------------------------------------------------
__global__ void aggw_kernel(const float* __restrict__ weight, float* __restrict__ out) {
    const int PER_B = DIMC*DIMC*KSZ*KSZ;   // 102400
    int idx = blockIdx.x * 256 + threadIdx.x;
    if (idx >= BATCH*PER_B) return;
    int b = idx / PER_B;
    int r = idx - b*PER_B;                 // (o,i,s)
    int o  = r / (DIMC*KSZ*KSZ);
    int r2 = r - o*(DIMC*KSZ*KSZ);
    int i  = r2 / (KSZ*KSZ);
    int s  = r2 - i*(KSZ*KSZ);
    float v = 0.f;
    #pragma unroll
    for (int k = 0; k < KBANK; k++)
        v += g_att[b*KBANK + k] * weight[(size_t)k*PER_B + r];
    // exact w_ret: (B*Cout, ks*ks, Cin)
    out[(size_t)OUT_OFFSET + ((size_t)(b*DIMC + o)*(KSZ*KSZ) + s)*DIMC + i] = v;
    // tf32 weight matrix for the GEMM: [b][s][ci][co]
    g_wmat[(((size_t)b*(KSZ*KSZ) + s)*DIMC + i)*DIMC + o] = wmma::__float_to_tf32(v);
}

// ---------------------------------------------------------------------------
// 4) Implicit-GEMM conv on tensor cores (tf32 wmma m16n16k8)
//    Block: 128 spatial (8 oy x 16 ox) x 64 cout, K=1600 in 50 chunks of 32.
// ---------------------------------------------------------------------------
struct Stage { float A[BM*LDA]; float Bv[BKC*LDB]; };
union ConvSmem { Stage st; float epi[BM*LDE]; };

__global__ __launch_bounds__(256) void conv_tc_kernel(float* __restrict__ out) {
    __shared__ ConvSmem sm;

    const int b   = blockIdx.z;
    const int tx  = blockIdx.x & 7;       // ox tile (16 wide)
    const int ty  = blockIdx.x >> 3;      // oy tile (8 tall)
    const int oy0 = ty * 8;
    const int ox0 = tx * 16;

    const int tid  = threadIdx.x;
    const int wid  = tid >> 5;
    const int wm   = wid >> 1;            // 0..3 : spatial 32-row group
    const int wn   = wid & 1;             // 0..1 : cout 32-col group

    const float* __restrict__ xb = g_xt + (size_t)b * HIN * WIN * DIMC;
    const float* __restrict__ wb = g_wmat + (size_t)b * (KSZ*KSZ) * DIMC * DIMC;

    wmma::fragment<wmma::accumulator, 16, 16, 8, float> acc[2][2];
    #pragma unroll
    for (int i = 0; i < 2; i++)
        #pragma unroll
        for (int j = 0; j < 2; j++) wmma::fill_fragment(acc[i][j], 0.0f);

    // Per-thread A staging geometry: 4 float4 per thread covering 128 pos x 32 ci
    int posj[4], cig4[4], oybj[4], oxbj[4];
    bool vsp[4];
    #pragma unroll
    for (int j = 0; j < 4; j++) {
        int f = j*256 + tid;              // 0..1023 float4 slots
        int pos = f >> 3;                 // 0..127
        int cig = f & 7;                  // which float4 within 32 ci
        int py = pos >> 4, px = pos & 15;
        int oy = oy0 + py, ox = ox0 + px;
        posj[j] = pos; cig4[j] = cig * 4;
        oybj[j] = oy*2 - 1; oxbj[j] = ox*2 - 1;
        vsp[j] = (oy < HO) && (ox < WO);
    }

    for (int s = 0; s < KSZ*KSZ; s++) {
        const int ky = s / KSZ, kx = s - (s/KSZ)*KSZ;
        #pragma unroll
        for (int ch = 0; ch < 2; ch++) {
            const int ci0 = ch * BKC;
            // --- load to registers (overlaps with previous chunk's MMA) ---
            float4 ra[4];
            #pragma unroll
            for (int j = 0; j < 4; j++) {
                int iy = oybj[j] + ky;
                int ix = oxbj[j] + kx;
                if (vsp[j] && (unsigned)iy < HIN && (unsigned)ix < WIN) {
                    ra[j] = *(const float4*)(xb + ((size_t)(iy*WIN + ix))*DIMC + ci0 + cig4[j]);
                } else {
                    ra[j] = make_float4(0.f, 0.f, 0.f, 0.f);
                }
            }
            float4 rb[2];
            const float* wsrc = wb + ((size_t)s*DIMC + ci0)*DIMC;   // 32x64 contiguous
            #pragma unroll
            for (int j = 0; j < 2; j++)
                rb[j] = *(const float4*)(wsrc + (j*256 + tid)*4);

            __syncthreads();
            // --- stores to smem ---
            #pragma unroll
            for (int j = 0; j < 4; j++)
                *(float4*)(&sm.st.A[posj[j]*LDA + cig4[j]]) = ra[j];
            #pragma unroll
            for (int j = 0; j < 2; j++) {
                int g = j*256 + tid;         // float4 slot in 32x64
                int row = g >> 4, col4 = g & 15;
                *(float4*)(&sm.st.Bv[row*LDB + col4*4]) = rb[j];
            }
            __syncthreads();

            // --- 4 k-steps of wmma ---
            #pragma unroll
            for (int kk = 0; kk < 4; kk++) {
                wmma::fragment<wmma::matrix_a, 16, 16, 8, wmma::precision::tf32, wmma::row_major> af[2];
                wmma::fragment<wmma::matrix_b, 16, 16, 8, wmma::precision::tf32, wmma::row_major> bf[2];
                #pragma unroll
                for (int i = 0; i < 2; i++)
                    wmma::load_matrix_sync(af[i], &sm.st.A[(wm*32 + i*16)*LDA + kk*8], LDA);
                #pragma unroll
                for (int j = 0; j < 2; j++)
                    wmma::load_matrix_sync(bf[j], &sm.st.Bv[(kk*8)*LDB + wn*32 + j*16], LDB);
                #pragma unroll
                for (int i = 0; i < 2; i++)
                    #pragma unroll
                    for (int j = 0; j < 2; j++)
                        wmma::mma_sync(acc[i][j], af[i], bf[j], acc[i][j]);
            }
        }
    }

    // --- epilogue: stage to smem, remap to (co, spatial), add bias ---
    __syncthreads();
    #pragma unroll
    for (int i = 0; i < 2; i++)
        #pragma unroll
        for (int j = 0; j < 2; j++)
            wmma::store_matrix_sync(&sm.epi[(wm*32 + i*16)*LDE + wn*32 + j*16],
                                    acc[i][j], LDE, wmma::mem_row_major);
    __syncthreads();

    #pragma unroll
    for (int it = 0; it < 32; it++) {
        int idx = it*256 + tid;           // 0..8191
        int pos = idx & 127;
        int co  = idx >> 7;
        int py = pos >> 4, px = pos & 15;
        int oy = oy0 + py, ox = ox0 + px;
        if (oy < HO && ox < WO) {
            out[((size_t)(b*DIMC + co))*OUT_SPATIAL + oy*WO + ox] =
                sm.epi[pos*LDE + co] + g_aggb[b*DIMC + co];
        }
    }
}

// ---------------------------------------------------------------------------
extern "C" void kernel_launch(void* const* d_in, const int* in_sizes, int n_in,
                              void* d_out, int out_size) {
    const float* x     = (const float*)d_in[0];
    const float* fc1_w = (const float*)d_in[1];
    const float* fc1_b = (const float*)d_in[2];
    const float* fc2_w = (const float*)d_in[3];
    const float* fc2_b = (const float*)d_in[4];
    const float* weight= (const float*)d_in[5];
    const float* bias  = (const float*)d_in[6];
    float* out = (float*)d_out;

    {
        dim3 g(WIN/64, HIN, BATCH);       // 4 x 256 x 16
        transpose_kernel<<<g, 256>>>(x);
    }
    pool_kernel<<<BATCH*DIMC, 256>>>(x);
    att_kernel<<<1, 32>>>(fc1_w, fc1_b, fc2_w, fc2_b, bias);
    {
        int n = BATCH*DIMC*DIMC*KSZ*KSZ;
        aggw_kernel<<<(n + 255)/256, 256>>>(weight, out);
    }
    {
        dim3 grid(8 * 16, 1, BATCH);      // 8 ox-tiles x 16 oy-tiles x 16 samples
        conv_tc_kernel<<<grid, 256>>>(out);
    }
    (void)in_sizes; (void)n_in; (void)out_size;
}

// round 5
// speedup vs baseline: 7.2709x; 3.2617x over previous
#include <cuda_runtime.h>
#include <cuda_fp16.h>
#include <mma.h>
#include <math.h>
#include <cstdint>
#include <cstdio>

using namespace nvcuda;

// Problem constants
#define DIMC   64
#define KBANK  4
#define BATCH  16
#define HIN    256
#define WIN    256
#define KSZ    5
#define HO     127
#define WO     127
#define OUT_SPATIAL (HO*WO)                       // 16129
#define OUT_OFFSET  (BATCH*DIMC*OUT_SPATIAL)      // start of w_ret in d_out

// Conv (implicit GEMM) tiling
#define BM 128          // spatial positions per block (8 oy x 16 ox)
#define BN 64           // couts per block
#define BKC 32          // cin chunk per stage
#define LDA 40          // sA leading dim (halves)  : 80 B/row
#define LDB 72          // sB leading dim (halves)  : 144 B/row
#define LDE 68          // epilogue leading dim (floats)
#define NCHUNK (KSZ*KSZ*2)   // 50

// Scratch (static device arrays — no allocations allowed)
__device__ float  g_pooled[BATCH*DIMC];
__device__ float  g_aggb[BATCH*DIMC];
__device__ float  g_att[BATCH*KBANK];
__device__ __half g_wmat[BATCH*KSZ*KSZ*DIMC*DIMC];          // [b][s][ci][co], fp16
__device__ __half g_xh[(size_t)BATCH*HIN*WIN*DIMC];         // NHWC fp16 (128 MB)

// ---------------------------------------------------------------------------
// cp.async helpers
// ---------------------------------------------------------------------------
__device__ __forceinline__ void cp16(unsigned saddr, const void* gptr, bool pred) {
    int sz = pred ? 16 : 0;
    asm volatile("cp.async.cg.shared.global [%0], [%1], 16, %2;\n"
                 :: "r"(saddr), "l"(gptr), "r"(sz));
}
__device__ __forceinline__ void cp_commit() {
    asm volatile("cp.async.commit_group;\n");
}
template<int N> __device__ __forceinline__ void cp_wait() {
    asm volatile("cp.async.wait_group %0;\n" :: "n"(N));
}

// ---------------------------------------------------------------------------
// 0) Transpose NCHW fp32 -> NHWC fp16
// ---------------------------------------------------------------------------
__global__ __launch_bounds__(256) void transpose_kernel(const float* __restrict__ x) {
    __shared__ float s[64][65];
    const int b = blockIdx.z, h = blockIdx.y, w0 = blockIdx.x * 64;
    const int tid = threadIdx.x;
    #pragma unroll
    for (int it = 0; it < 16; it++) {
        int f = it*256 + tid;
        int c = f >> 6, wl = f & 63;
        s[c][wl] = x[(((size_t)(b*DIMC + c))*HIN + h)*WIN + w0 + wl];
    }
    __syncthreads();
    #pragma unroll
    for (int it = 0; it < 8; it++) {
        int f = it*256 + tid;          // 0..2047 : (wl, c-pair)
        int wl = f >> 5, c2 = (f & 31) * 2;
        __half2 v = __floats2half2_rn(s[c2][wl], s[c2+1][wl]);
        *(__half2*)(&g_xh[(((size_t)b*HIN + h)*WIN + (w0 + wl))*DIMC + c2]) = v;
    }
}

// ---------------------------------------------------------------------------
// 1) Global average pool (fp32, exact): one block per (b,c) plane
// ---------------------------------------------------------------------------
__global__ void pool_kernel(const float* __restrict__ x) {
    int plane = blockIdx.x;
    const float4* p = (const float4*)(x + (size_t)plane * (HIN*WIN));
    float s = 0.f;
    for (int i = threadIdx.x; i < (HIN*WIN)/4; i += 256) {
        float4 v = p[i];
        s += (v.x + v.y) + (v.z + v.w);
    }
    #pragma unroll
    for (int o = 16; o > 0; o >>= 1) s += __shfl_xor_sync(0xffffffffu, s, o);
    __shared__ float ws[8];
    if ((threadIdx.x & 31) == 0) ws[threadIdx.x >> 5] = s;
    __syncthreads();
    if (threadIdx.x == 0) {
        float t = 0.f;
        #pragma unroll
        for (int i = 0; i < 8; i++) t += ws[i];
        g_pooled[plane] = t * (1.0f / (float)(HIN*WIN));
    }
}

// ---------------------------------------------------------------------------
// 2) Attention MLP + softmax + aggregated bias
// ---------------------------------------------------------------------------
__global__ void att_kernel(const float* __restrict__ fc1_w, const float* __restrict__ fc1_b,
                           const float* __restrict__ fc2_w, const float* __restrict__ fc2_b,
                           const float* __restrict__ bias) {
    int b = threadIdx.x;
    if (b >= BATCH) return;
    float a[KBANK];
    #pragma unroll
    for (int k = 0; k < KBANK; k++) {
        float s = fc1_b[k];
        for (int c = 0; c < DIMC; c++) s += fc1_w[k*DIMC + c] * g_pooled[b*DIMC + c];
        a[k] = fmaxf(s, 0.f);
    }
    float l[KBANK]; float mx = -1e30f;
    #pragma unroll
    for (int k = 0; k < KBANK; k++) {
        float s = fc2_b[k];
        #pragma unroll
        for (int j = 0; j < KBANK; j++) s += fc2_w[k*KBANK + j] * a[j];
        l[k] = s; mx = fmaxf(mx, s);
    }
    float den = 0.f;
    #pragma unroll
    for (int k = 0; k < KBANK; k++) { l[k] = expf(l[k] - mx); den += l[k]; }
    float inv = 1.0f / den;
    #pragma unroll
    for (int k = 0; k < KBANK; k++) { l[k] *= inv; g_att[b*KBANK + k] = l[k]; }
    for (int o = 0; o < DIMC; o++) {
        float s = 0.f;
        #pragma unroll
        for (int k = 0; k < KBANK; k++) s += l[k] * bias[k*DIMC + o];
        g_aggb[b*DIMC + o] = s;
    }
}

// ---------------------------------------------------------------------------
// 3) Mix kernel banks; exact fp32 w_ret to out, fp16 wmat for conv
// ---------------------------------------------------------------------------
__global__ void aggw_kernel(const float* __restrict__ weight, float* __restrict__ out) {
    const int PER_B = DIMC*DIMC*KSZ*KSZ;   // 102400
    int idx = blockIdx.x * 256 + threadIdx.x;
    if (idx >= BATCH*PER_B) return;
    int b = idx / PER_B;
    int r = idx - b*PER_B;                 // (o,i,s)
    int o  = r / (DIMC*KSZ*KSZ);
    int r2 = r - o*(DIMC*KSZ*KSZ);
    int i  = r2 / (KSZ*KSZ);
    int s  = r2 - i*(KSZ*KSZ);
    float v = 0.f;
    #pragma unroll
    for (int k = 0; k < KBANK; k++)
        v += g_att[b*KBANK + k] * weight[(size_t)k*PER_B + r];
    out[(size_t)OUT_OFFSET + ((size_t)(b*DIMC + o)*(KSZ*KSZ) + s)*DIMC + i] = v;
    g_wmat[(((size_t)b*(KSZ*KSZ) + s)*DIMC + i)*DIMC + o] = __float2half_rn(v);
}

// ---------------------------------------------------------------------------
// 4) Implicit-GEMM conv, fp16 HMMA, cp.async double-buffered.
//    Block: 128 spatial (8 oy x 16 ox) x 64 cout; K=1600 in 50 chunks of 32.
// ---------------------------------------------------------------------------
struct alignas(16) Stage { __half A[BM*LDA]; __half Bv[BKC*LDB]; };
union ConvSmem { Stage st[2]; float epi[BM*LDE]; };

__global__ __launch_bounds__(256) void conv_tc_kernel(float* __restrict__ out) {
    __shared__ ConvSmem sm;

    const int b   = blockIdx.z;
    const int tx  = blockIdx.x & 7;       // ox tile (16 wide)
    const int ty  = blockIdx.x >> 3;      // oy tile (8 tall)
    const int oy0 = ty * 8;
    const int ox0 = tx * 16;

    const int tid = threadIdx.x;
    const int wid = tid >> 5;
    const int wm  = wid >> 1;             // 0..3 : spatial 32-row group
    const int wn  = wid & 1;              // 0..1 : cout 32-col group

    const __half* __restrict__ xb  = g_xh  + (size_t)b * HIN * WIN * DIMC;
    const __half* __restrict__ wbh = g_wmat + (size_t)b * (KSZ*KSZ) * DIMC * DIMC;

    wmma::fragment<wmma::accumulator, 16, 16, 16, float> acc[2][2];
    #pragma unroll
    for (int i = 0; i < 2; i++)
        #pragma unroll
        for (int j = 0; j < 2; j++) wmma::fill_fragment(acc[i][j], 0.0f);

    // Per-thread A staging geometry: 2 cp.async slots of 16B (8 halves) each.
    int aOff[2], ibY[2], ibX[2], cig8[2];
    bool vs[2];
    #pragma unroll
    for (int j = 0; j < 2; j++) {
        int f = j*256 + tid;              // 0..511  (128 pos x 4 slots)
        int pos = f >> 2, cig = f & 3;
        int py = pos >> 4, px = pos & 15;
        int oy = oy0 + py, ox = ox0 + px;
        aOff[j] = pos*LDA + cig*8;
        cig8[j] = cig*8;
        ibY[j] = oy*2 - 1; ibX[j] = ox*2 - 1;
        vs[j] = (oy < HO) && (ox < WO);
    }
    // B slot
    const int bRow = tid >> 3;
    const int bCol = (tid & 7) * 8;
    const int bOff = bRow*LDB + bCol;

    unsigned aBase[2], bBase[2];
    #pragma unroll
    for (int u = 0; u < 2; u++) {
        aBase[u] = (unsigned)__cvta_generic_to_shared(&sm.st[u].A[0]);
        bBase[u] = (unsigned)__cvta_generic_to_shared(&sm.st[u].Bv[0]);
    }

    // issue chunk c into buffer buf
    auto issue = [&](int c_, int buf_) {
        int s2 = c_ >> 1, ch = c_ & 1;
        int ky = s2 / KSZ, kx = s2 - (s2/KSZ)*KSZ;
        #pragma unroll
        for (int j = 0; j < 2; j++) {
            int iy = ibY[j] + ky, ix = ibX[j] + kx;
            bool p = vs[j] && ((unsigned)iy < HIN) && ((unsigned)ix < WIN);
            const __half* g = p ? (xb + (((size_t)iy*WIN + ix)*DIMC + ch*BKC + cig8[j])) : xb;
            cp16(aBase[buf_] + (unsigned)aOff[j]*2u, g, p);
        }
        cp16(bBase[buf_] + (unsigned)bOff*2u,
             wbh + (((size_t)s2*DIMC + ch*BKC + bRow)*DIMC + bCol), true);
        cp_commit();
    };

    issue(0, 0);
    for (int c = 0; c < NCHUNK; c++) {
        if (c + 1 < NCHUNK) { issue(c + 1, (c + 1) & 1); cp_wait<1>(); }
        else                { cp_wait<0>(); }
        __syncthreads();

        const __half* sA = sm.st[c & 1].A;
        const __half* sB = sm.st[c & 1].Bv;
        #pragma unroll
        for (int kk = 0; kk < 2; kk++) {
            wmma::fragment<wmma::matrix_a, 16, 16, 16, __half, wmma::row_major> af[2];
            wmma::fragment<wmma::matrix_b, 16, 16, 16, __half, wmma::row_major> bf[2];
            #pragma unroll
            for (int i = 0; i < 2; i++)
                wmma::load_matrix_sync(af[i], &sA[(wm*32 + i*16)*LDA + kk*16], LDA);
            #pragma unroll
            for (int j = 0; j < 2; j++)
                wmma::load_matrix_sync(bf[j], &sB[(kk*16)*LDB + wn*32 + j*16], LDB);
            #pragma unroll
            for (int i = 0; i < 2; i++)
                #pragma unroll
                for (int j = 0; j < 2; j++)
                    wmma::mma_sync(acc[i][j], af[i], bf[j], acc[i][j]);
        }
        __syncthreads();
    }

    // --- epilogue: stage to smem, remap to (co, spatial), add bias ---
    #pragma unroll
    for (int i = 0; i < 2; i++)
        #pragma unroll
        for (int j = 0; j < 2; j++)
            wmma::store_matrix_sync(&sm.epi[(wm*32 + i*16)*LDE + wn*32 + j*16],
                                    acc[i][j], LDE, wmma::mem_row_major);
    __syncthreads();

    #pragma unroll
    for (int it = 0; it < 32; it++) {
        int idx = it*256 + tid;           // 0..8191
        int pos = idx & 127;
        int co  = idx >> 7;
        int py = pos >> 4, px = pos & 15;
        int oy = oy0 + py, ox = ox0 + px;
        if (oy < HO && ox < WO) {
            out[((size_t)(b*DIMC + co))*OUT_SPATIAL + oy*WO + ox] =
                sm.epi[pos*LDE + co] + g_aggb[b*DIMC + co];
        }
    }
}

// ---------------------------------------------------------------------------
extern "C" void kernel_launch(void* const* d_in, const int* in_sizes, int n_in,
                              void* d_out, int out_size) {
    const float* x     = (const float*)d_in[0];
    const float* fc1_w = (const float*)d_in[1];
    const float* fc1_b = (const float*)d_in[2];
    const float* fc2_w = (const float*)d_in[3];
    const float* fc2_b = (const float*)d_in[4];
    const float* weight= (const float*)d_in[5];
    const float* bias  = (const float*)d_in[6];
    float* out = (float*)d_out;

    {
        dim3 g(WIN/64, HIN, BATCH);       // 4 x 256 x 16
        transpose_kernel<<<g, 256>>>(x);
    }
    pool_kernel<<<BATCH*DIMC, 256>>>(x);
    att_kernel<<<1, 32>>>(fc1_w, fc1_b, fc2_w, fc2_b, bias);
    {
        int n = BATCH*DIMC*DIMC*KSZ*KSZ;
        aggw_kernel<<<(n + 255)/256, 256>>>(weight, out);
    }
    {
        dim3 grid(8 * 16, 1, BATCH);      // 128 spatial tiles x 16 samples
        conv_tc_kernel<<<grid, 256>>>(out);
    }
    (void)in_sizes; (void)n_in; (void)out_size;
}

// round 6
// speedup vs baseline: 7.9463x; 1.0929x over previous
#include <cuda_runtime.h>
#include <cuda_fp16.h>
#include <mma.h>
#include <math.h>
#include <cstdint>
#include <cstdio>

using namespace nvcuda;

// Problem constants
#define DIMC   64
#define KBANK  4
#define BATCH  16
#define HIN    256
#define WIN    256
#define KSZ    5
#define HO     127
#define WO     127
#define OUT_SPATIAL (HO*WO)                       // 16129
#define OUT_OFFSET  (BATCH*DIMC*OUT_SPATIAL)      // start of w_ret in d_out

// Conv (implicit GEMM) tiling
#define BM 128          // spatial positions per block (8 oy x 16 ox)
#define BN 64           // couts per block
#define BKC 32          // cin chunk per stage
#define LDA 40          // sA leading dim (halves)  : 80 B/row
#define LDB 72          // sB leading dim (halves)  : 144 B/row
#define LDE 68          // epilogue leading dim (floats)
#define NCHUNK (KSZ*KSZ*2)   // 50
#define STAGES 4

// Scratch (static device arrays — no allocations allowed)
__device__ float  g_pooled[BATCH*DIMC];
__device__ float  g_aggb[BATCH*DIMC];
__device__ float  g_att[BATCH*KBANK];
__device__ __half g_wmat[BATCH*KSZ*KSZ*DIMC*DIMC];          // [b][s][ci][co], fp16
__device__ __half g_xh[(size_t)BATCH*HIN*WIN*DIMC];         // NHWC fp16 (128 MB)

// ---------------------------------------------------------------------------
// cp.async helpers
// ---------------------------------------------------------------------------
__device__ __forceinline__ void cp16(unsigned saddr, const void* gptr, bool pred) {
    int sz = pred ? 16 : 0;
    asm volatile("cp.async.cg.shared.global [%0], [%1], 16, %2;\n"
                 :: "r"(saddr), "l"(gptr), "r"(sz));
}
__device__ __forceinline__ void cp_commit() {
    asm volatile("cp.async.commit_group;\n");
}
template<int N> __device__ __forceinline__ void cp_wait() {
    asm volatile("cp.async.wait_group %0;\n" :: "n"(N));
}

// ---------------------------------------------------------------------------
// 0a) Zero the pooled accumulator (tiny)
// ---------------------------------------------------------------------------
__global__ void zero_pool_kernel() {
    g_pooled[threadIdx.x] = 0.f;
}

// ---------------------------------------------------------------------------
// 0b) Transpose NCHW fp32 -> NHWC fp16, fused global-avg-pool partials
// ---------------------------------------------------------------------------
__global__ __launch_bounds__(256) void transpose_kernel(const float* __restrict__ x) {
    __shared__ float s[64][65];
    const int b = blockIdx.z, h = blockIdx.y, w0 = blockIdx.x * 64;
    const int tid = threadIdx.x;
    #pragma unroll
    for (int it = 0; it < 16; it++) {
        int f = it*256 + tid;
        int c = f >> 6, wl = f & 63;
        s[c][wl] = x[(((size_t)(b*DIMC + c))*HIN + h)*WIN + w0 + wl];
    }
    __syncthreads();
    // transposed fp16 store
    #pragma unroll
    for (int it = 0; it < 8; it++) {
        int f = it*256 + tid;          // 0..2047 : (wl, c-pair)
        int wl = f >> 5, c2 = (f & 31) * 2;
        __half2 v = __floats2half2_rn(s[c2][wl], s[c2+1][wl]);
        *(__half2*)(&g_xh[(((size_t)b*HIN + h)*WIN + (w0 + wl))*DIMC + c2]) = v;
    }
    // fused pool partial: thread t -> channel c = t>>2, quarter q = t&3
    {
        int c = tid >> 2, q = tid & 3;
        float ps = 0.f;
        #pragma unroll
        for (int i = 0; i < 16; i++) ps += s[c][q*16 + i];
        ps += __shfl_xor_sync(0xffffffffu, ps, 1);
        ps += __shfl_xor_sync(0xffffffffu, ps, 2);
        if (q == 0)
            atomicAdd(&g_pooled[b*DIMC + c], ps * (1.0f / (float)(HIN*WIN)));
    }
}

// ---------------------------------------------------------------------------
// 2) Attention MLP + softmax + aggregated bias
// ---------------------------------------------------------------------------
__global__ void att_kernel(const float* __restrict__ fc1_w, const float* __restrict__ fc1_b,
                           const float* __restrict__ fc2_w, const float* __restrict__ fc2_b,
                           const float* __restrict__ bias) {
    int b = threadIdx.x;
    if (b >= BATCH) return;
    float a[KBANK];
    #pragma unroll
    for (int k = 0; k < KBANK; k++) {
        float s = fc1_b[k];
        for (int c = 0; c < DIMC; c++) s += fc1_w[k*DIMC + c] * g_pooled[b*DIMC + c];
        a[k] = fmaxf(s, 0.f);
    }
    float l[KBANK]; float mx = -1e30f;
    #pragma unroll
    for (int k = 0; k < KBANK; k++) {
        float s = fc2_b[k];
        #pragma unroll
        for (int j = 0; j < KBANK; j++) s += fc2_w[k*KBANK + j] * a[j];
        l[k] = s; mx = fmaxf(mx, s);
    }
    float den = 0.f;
    #pragma unroll
    for (int k = 0; k < KBANK; k++) { l[k] = expf(l[k] - mx); den += l[k]; }
    float inv = 1.0f / den;
    #pragma unroll
    for (int k = 0; k < KBANK; k++) { l[k] *= inv; g_att[b*KBANK + k] = l[k]; }
    for (int o = 0; o < DIMC; o++) {
        float s = 0.f;
        #pragma unroll
        for (int k = 0; k < KBANK; k++) s += l[k] * bias[k*DIMC + o];
        g_aggb[b*DIMC + o] = s;
    }
}

// ---------------------------------------------------------------------------
// 3) Mix kernel banks; exact fp32 w_ret to out, fp16 wmat for conv
// ---------------------------------------------------------------------------
__global__ void aggw_kernel(const float* __restrict__ weight, float* __restrict__ out) {
    const int PER_B = DIMC*DIMC*KSZ*KSZ;   // 102400
    int idx = blockIdx.x * 256 + threadIdx.x;
    if (idx >= BATCH*PER_B) return;
    int b = idx / PER_B;
    int r = idx - b*PER_B;                 // (o,i,s)
    int o  = r / (DIMC*KSZ*KSZ);
    int r2 = r - o*(DIMC*KSZ*KSZ);
    int i  = r2 / (KSZ*KSZ);
    int s  = r2 - i*(KSZ*KSZ);
    float v = 0.f;
    #pragma unroll
    for (int k = 0; k < KBANK; k++)
        v += g_att[b*KBANK + k] * weight[(size_t)k*PER_B + r];
    out[(size_t)OUT_OFFSET + ((size_t)(b*DIMC + o)*(KSZ*KSZ) + s)*DIMC + i] = v;
    g_wmat[(((size_t)b*(KSZ*KSZ) + s)*DIMC + i)*DIMC + o] = __float2half_rn(v);
}

// ---------------------------------------------------------------------------
// 4) Implicit-GEMM conv, fp16 HMMA, 4-stage cp.async ring, 1 barrier/chunk.
//    Block: 128 spatial (8 oy x 16 ox) x 64 cout; K=1600 in 50 chunks of 32.
// ---------------------------------------------------------------------------
struct alignas(16) Stage { __half A[BM*LDA]; __half Bv[BKC*LDB]; };
union ConvSmem { Stage st[STAGES]; float epi[BM*LDE]; };

__global__ __launch_bounds__(256) void conv_tc_kernel(float* __restrict__ out) {
    __shared__ ConvSmem sm;

    const int b   = blockIdx.z;
    const int tx  = blockIdx.x & 7;       // ox tile (16 wide)
    const int ty  = blockIdx.x >> 3;      // oy tile (8 tall)
    const int oy0 = ty * 8;
    const int ox0 = tx * 16;

    const int tid = threadIdx.x;
    const int wid = tid >> 5;
    const int wm  = wid >> 1;             // 0..3 : spatial 32-row group
    const int wn  = wid & 1;              // 0..1 : cout 32-col group

    const __half* __restrict__ xb  = g_xh  + (size_t)b * HIN * WIN * DIMC;
    const __half* __restrict__ wbh = g_wmat + (size_t)b * (KSZ*KSZ) * DIMC * DIMC;

    wmma::fragment<wmma::accumulator, 16, 16, 16, float> acc[2][2];
    #pragma unroll
    for (int i = 0; i < 2; i++)
        #pragma unroll
        for (int j = 0; j < 2; j++) wmma::fill_fragment(acc[i][j], 0.0f);

    // Per-thread A staging geometry: 2 cp.async slots of 16B (8 halves) each.
    int aOff[2], ibY[2], ibX[2], cig8[2];
    bool vs[2];
    #pragma unroll
    for (int j = 0; j < 2; j++) {
        int f = j*256 + tid;              // 0..511  (128 pos x 4 slots)
        int pos = f >> 2, cig = f & 3;
        int py = pos >> 4, px = pos & 15;
        int oy = oy0 + py, ox = ox0 + px;
        aOff[j] = pos*LDA + cig*8;
        cig8[j] = cig*8;
        ibY[j] = oy*2 - 1; ibX[j] = ox*2 - 1;
        vs[j] = (oy < HO) && (ox < WO);
    }
    // B slot
    const int bRow = tid >> 3;
    const int bCol = (tid & 7) * 8;
    const int bOff = bRow*LDB + bCol;

    unsigned aBase[STAGES], bBase[STAGES];
    #pragma unroll
    for (int u = 0; u < STAGES; u++) {
        aBase[u] = (unsigned)__cvta_generic_to_shared(&sm.st[u].A[0]);
        bBase[u] = (unsigned)__cvta_generic_to_shared(&sm.st[u].Bv[0]);
    }

    // issue chunk c into stage buf
    auto issue = [&](int c_, int buf_) {
        int s2 = c_ >> 1, ch = c_ & 1;
        int ky = s2 / KSZ, kx = s2 - (s2/KSZ)*KSZ;
        #pragma unroll
        for (int j = 0; j < 2; j++) {
            int iy = ibY[j] + ky, ix = ibX[j] + kx;
            bool p = vs[j] && ((unsigned)iy < HIN) && ((unsigned)ix < WIN);
            const __half* g = p ? (xb + (((size_t)iy*WIN + ix)*DIMC + ch*BKC + cig8[j])) : xb;
            cp16(aBase[buf_] + (unsigned)aOff[j]*2u, g, p);
        }
        cp16(bBase[buf_] + (unsigned)bOff*2u,
             wbh + (((size_t)s2*DIMC + ch*BKC + bRow)*DIMC + bCol), true);
        cp_commit();
    };

    issue(0, 0); issue(1, 1); issue(2, 2);

    for (int c = 0; c < NCHUNK; c++) {
        cp_wait<2>();          // group c complete (c+1, c+2 may be pending)
        __syncthreads();       // publish stage c; all warps done with stage (c-1)&3
        if (c + 3 < NCHUNK) issue(c + 3, (c + 3) & 3);
        else                cp_commit();     // keep group count uniform

        const __half* sA = sm.st[c & 3].A;
        const __half* sB = sm.st[c & 3].Bv;
        #pragma unroll
        for (int kk = 0; kk < 2; kk++) {
            wmma::fragment<wmma::matrix_a, 16, 16, 16, __half, wmma::row_major> af[2];
            wmma::fragment<wmma::matrix_b, 16, 16, 16, __half, wmma::row_major> bf[2];
            #pragma unroll
            for (int i = 0; i < 2; i++)
                wmma::load_matrix_sync(af[i], &sA[(wm*32 + i*16)*LDA + kk*16], LDA);
            #pragma unroll
            for (int j = 0; j < 2; j++)
                wmma::load_matrix_sync(bf[j], &sB[(kk*16)*LDB + wn*32 + j*16], LDB);
            #pragma unroll
            for (int i = 0; i < 2; i++)
                #pragma unroll
                for (int j = 0; j < 2; j++)
                    wmma::mma_sync(acc[i][j], af[i], bf[j], acc[i][j]);
        }
    }

    // --- epilogue: stage to smem, remap to (co, spatial), add bias ---
    __syncthreads();           // all warps done reading stages before epi overwrite
    #pragma unroll
    for (int i = 0; i < 2; i++)
        #pragma unroll
        for (int j = 0; j < 2; j++)
            wmma::store_matrix_sync(&sm.epi[(wm*32 + i*16)*LDE + wn*32 + j*16],
                                    acc[i][j], LDE, wmma::mem_row_major);
    __syncthreads();

    #pragma unroll
    for (int it = 0; it < 32; it++) {
        int idx = it*256 + tid;           // 0..8191
        int pos = idx & 127;
        int co  = idx >> 7;
        int py = pos >> 4, px = pos & 15;
        int oy = oy0 + py, ox = ox0 + px;
        if (oy < HO && ox < WO) {
            out[((size_t)(b*DIMC + co))*OUT_SPATIAL + oy*WO + ox] =
                sm.epi[pos*LDE + co] + g_aggb[b*DIMC + co];
        }
    }
}

// ---------------------------------------------------------------------------
extern "C" void kernel_launch(void* const* d_in, const int* in_sizes, int n_in,
                              void* d_out, int out_size) {
    const float* x     = (const float*)d_in[0];
    const float* fc1_w = (const float*)d_in[1];
    const float* fc1_b = (const float*)d_in[2];
    const float* fc2_w = (const float*)d_in[3];
    const float* fc2_b = (const float*)d_in[4];
    const float* weight= (const float*)d_in[5];
    const float* bias  = (const float*)d_in[6];
    float* out = (float*)d_out;

    zero_pool_kernel<<<1, BATCH*DIMC>>>();
    {
        dim3 g(WIN/64, HIN, BATCH);       // 4 x 256 x 16
        transpose_kernel<<<g, 256>>>(x);
    }
    att_kernel<<<1, 32>>>(fc1_w, fc1_b, fc2_w, fc2_b, bias);
    {
        int n = BATCH*DIMC*DIMC*KSZ*KSZ;
        aggw_kernel<<<(n + 255)/256, 256>>>(weight, out);
    }
    {
        dim3 grid(8 * 16, 1, BATCH);      // 128 spatial tiles x 16 samples
        conv_tc_kernel<<<grid, 256>>>(out);
    }
    (void)in_sizes; (void)n_in; (void)out_size;
}